// round 1
// baseline (speedup 1.0000x reference)
#include <cuda_runtime.h>

#define MAX_LAYERS 64
#define TPB 256
#define PTS_PER_THREAD 8          // 4 float4 per thread (2 points per float4)
#define F4_PER_THREAD (PTS_PER_THREAD / 2)

__device__ __forceinline__ float tanh_fast(float x) {
    float y;
    asm("tanh.approx.f32 %0, %1;" : "=f"(y) : "f"(x));
    return y;
}

__global__ __launch_bounds__(TPB) void nignet_kernel(
    const float4* __restrict__ pts,   // (N,2) as float4 pairs
    const float* __restrict__ Ws,     // (L,2,2)
    const float* __restrict__ bs,     // (L,2)
    const float* __restrict__ fW,     // (2,2)
    float4* __restrict__ out,
    int nf4,                          // N/2 float4 count
    int layers)
{
    __shared__ float sw[MAX_LAYERS * 4];
    __shared__ float sb[MAX_LAYERS * 2];
    __shared__ float sf[4];

    const int tid = threadIdx.x;
    if (tid < layers * 4) sw[tid] = Ws[tid];
    if (tid < layers * 2) sb[tid] = bs[tid];
    if (tid < 4)          sf[tid] = fW[tid];
    __syncthreads();

    const int base4 = blockIdx.x * (TPB * F4_PER_THREAD);

    float x0[PTS_PER_THREAD], x1[PTS_PER_THREAD];
    bool valid[F4_PER_THREAD];

    #pragma unroll
    for (int i = 0; i < F4_PER_THREAD; ++i) {
        int idx = base4 + i * TPB + tid;
        valid[i] = (idx < nf4);
        float4 v = valid[i] ? pts[idx] : make_float4(0.f, 0.f, 0.f, 0.f);
        x0[2 * i]     = v.x;  x1[2 * i]     = v.y;
        x0[2 * i + 1] = v.z;  x1[2 * i + 1] = v.w;
    }

    // 64 layers: keep the loop rolled so the body stays inside L0 I$.
    #pragma unroll 1
    for (int l = 0; l < layers; ++l) {
        const float w00 = sw[4 * l + 0];
        const float w01 = sw[4 * l + 1];
        const float w10 = sw[4 * l + 2];
        const float w11 = sw[4 * l + 3];
        const float b0  = sb[2 * l + 0];
        const float b1  = sb[2 * l + 1];
        #pragma unroll
        for (int i = 0; i < PTS_PER_THREAD; ++i) {
            float y0 = fmaf(w00, x0[i], fmaf(w01, x1[i], b0));
            float y1 = fmaf(w10, x0[i], fmaf(w11, x1[i], b1));
            float t0 = tanh_fast(y0);
            float t1 = tanh_fast(y1);
            x0[i] = (t0 + y0) * 0.5f;
            x1[i] = (t1 + y1) * 0.5f;
        }
    }

    const float f00 = sf[0], f01 = sf[1], f10 = sf[2], f11 = sf[3];

    #pragma unroll
    for (int i = 0; i < F4_PER_THREAD; ++i) {
        float4 v;
        {
            float o0 = fmaf(f00, x0[2 * i], f01 * x1[2 * i]);
            float o1 = fmaf(f10, x0[2 * i], f11 * x1[2 * i]);
            float s  = fmaf(o0, o0, o1 * o1);
            float inv = rsqrtf(s);
            inv = inv * fmaf(-0.5f * s * inv, inv, 1.5f);   // one Newton step
            if (s < 1e-24f) inv = 1e12f;                    // eps=1e-12 clamp
            v.x = o0 * inv;
            v.y = o1 * inv;
        }
        {
            float o0 = fmaf(f00, x0[2 * i + 1], f01 * x1[2 * i + 1]);
            float o1 = fmaf(f10, x0[2 * i + 1], f11 * x1[2 * i + 1]);
            float s  = fmaf(o0, o0, o1 * o1);
            float inv = rsqrtf(s);
            inv = inv * fmaf(-0.5f * s * inv, inv, 1.5f);
            if (s < 1e-24f) inv = 1e12f;
            v.z = o0 * inv;
            v.w = o1 * inv;
        }
        int idx = base4 + i * TPB + tid;
        if (valid[i]) out[idx] = v;
    }
}

extern "C" void kernel_launch(void* const* d_in, const int* in_sizes, int n_in,
                              void* d_out, int out_size) {
    // metadata order: T(1), closed_manifold(N*2), Ws(L*4), bs(L*2), final_W(4)
    const float* pts = (const float*)d_in[1];
    const float* Ws  = (const float*)d_in[2];
    const float* bs  = (const float*)d_in[3];
    const float* fW  = (const float*)d_in[4];
    float* out = (float*)d_out;

    const int n      = in_sizes[1] / 2;     // number of points
    const int layers = in_sizes[2] / 4;     // 64
    const int nf4    = n / 2;               // float4 count (N even)

    const int f4_per_block = TPB * F4_PER_THREAD;
    const int grid = (nf4 + f4_per_block - 1) / f4_per_block;

    nignet_kernel<<<grid, TPB>>>(
        (const float4*)pts, Ws, bs, fW, (float4*)out, nf4, layers);
}

// round 2
// speedup vs baseline: 1.0600x; 1.0600x over previous
#include <cuda_runtime.h>

#define MAX_LAYERS 64
#define TPB 256
#define PTS_PER_THREAD 8          // 4 float4 per thread (2 points per float4)
#define F4_PER_THREAD (PTS_PER_THREAD / 2)

__device__ __forceinline__ float tanh_fast(float x) {
    float y;
    asm("tanh.approx.f32 %0, %1;" : "=f"(y) : "f"(x));
    return y;
}

__global__ __launch_bounds__(TPB) void nignet_kernel(
    const float4* __restrict__ pts,   // (N,2) as float4 pairs
    const float* __restrict__ Ws,     // (L,2,2)
    const float* __restrict__ bs,     // (L,2)
    const float* __restrict__ fW,     // (2,2)
    float4* __restrict__ out,
    int nf4,                          // N/2 float4 count
    int layers)
{
    // Prescaled weights: layer 0 keeps W, layers >=1 store 0.5*W.
    // We iterate z_l = 2*x_l:  y = (W/2) z + b,  z' = tanh(y) + y.
    // Final normalize is scale-invariant, so the 2x on z never needs undoing.
    __shared__ float4 sw4[MAX_LAYERS];
    __shared__ float2 sb2[MAX_LAYERS];
    __shared__ float  sf[4];

    const int tid = threadIdx.x;
    if (tid < layers * 4) {
        float v = Ws[tid];
        ((float*)sw4)[tid] = (tid >= 4) ? v * 0.5f : v;
    }
    if (tid < layers * 2) ((float*)sb2)[tid] = bs[tid];
    if (tid < 4)          sf[tid] = fW[tid];
    __syncthreads();

    const int base4 = blockIdx.x * (TPB * F4_PER_THREAD);

    float x0[PTS_PER_THREAD], x1[PTS_PER_THREAD];
    bool valid[F4_PER_THREAD];

    #pragma unroll
    for (int i = 0; i < F4_PER_THREAD; ++i) {
        int idx = base4 + i * TPB + tid;
        valid[i] = (idx < nf4);
        float4 v = valid[i] ? pts[idx] : make_float4(0.f, 0.f, 0.f, 0.f);
        x0[2 * i]     = v.x;  x1[2 * i]     = v.y;
        x0[2 * i + 1] = v.z;  x1[2 * i + 1] = v.w;
    }

    // Rolled layer loop: body stays inside L0 I$.
    #pragma unroll 1
    for (int l = 0; l < layers; ++l) {
        const float4 w = sw4[l];
        const float2 b = sb2[l];
        #pragma unroll
        for (int i = 0; i < PTS_PER_THREAD; ++i) {
            float y0 = fmaf(w.x, x0[i], fmaf(w.y, x1[i], b.x));
            float y1 = fmaf(w.z, x0[i], fmaf(w.w, x1[i], b.y));
            float t0 = tanh_fast(y0);
            float t1 = tanh_fast(y1);
            x0[i] = t0 + y0;          // z' = tanh(y) + y   (no *0.5)
            x1[i] = t1 + y1;
        }
    }

    const float f00 = sf[0], f01 = sf[1], f10 = sf[2], f11 = sf[3];

    #pragma unroll
    for (int i = 0; i < F4_PER_THREAD; ++i) {
        float4 v;
        {
            float o0 = fmaf(f00, x0[2 * i], f01 * x1[2 * i]);
            float o1 = fmaf(f10, x0[2 * i], f11 * x1[2 * i]);
            float s  = fmaf(o0, o0, o1 * o1);
            float inv = rsqrtf(s);
            inv = inv * fmaf(-0.5f * s * inv, inv, 1.5f);   // one Newton step
            if (s < 1e-24f) inv = 1e12f;                    // eps clamp
            v.x = o0 * inv;
            v.y = o1 * inv;
        }
        {
            float o0 = fmaf(f00, x0[2 * i + 1], f01 * x1[2 * i + 1]);
            float o1 = fmaf(f10, x0[2 * i + 1], f11 * x1[2 * i + 1]);
            float s  = fmaf(o0, o0, o1 * o1);
            float inv = rsqrtf(s);
            inv = inv * fmaf(-0.5f * s * inv, inv, 1.5f);
            if (s < 1e-24f) inv = 1e12f;
            v.z = o0 * inv;
            v.w = o1 * inv;
        }
        int idx = base4 + i * TPB + tid;
        if (valid[i]) out[idx] = v;
    }
}

extern "C" void kernel_launch(void* const* d_in, const int* in_sizes, int n_in,
                              void* d_out, int out_size) {
    // metadata order: T(1), closed_manifold(N*2), Ws(L*4), bs(L*2), final_W(4)
    const float* pts = (const float*)d_in[1];
    const float* Ws  = (const float*)d_in[2];
    const float* bs  = (const float*)d_in[3];
    const float* fW  = (const float*)d_in[4];
    float* out = (float*)d_out;

    const int n      = in_sizes[1] / 2;     // number of points
    const int layers = in_sizes[2] / 4;     // 64
    const int nf4    = n / 2;               // float4 count (N even)

    const int f4_per_block = TPB * F4_PER_THREAD;
    const int grid = (nf4 + f4_per_block - 1) / f4_per_block;

    nignet_kernel<<<grid, TPB>>>(
        (const float4*)pts, Ws, bs, fW, (float4*)out, nf4, layers);
}

// round 3
// speedup vs baseline: 1.3189x; 1.2442x over previous
#include <cuda_runtime.h>
#include <cuda_fp16.h>

#define TPB 256
#define MAX_LAYERS 64

__device__ __forceinline__ __half2 tanh_h2(__half2 x) {
    __half2 y;
    asm("tanh.approx.f16x2 %0, %1;"
        : "=r"(*reinterpret_cast<unsigned int*>(&y))
        : "r"(*reinterpret_cast<const unsigned int*>(&x)));
    return y;
}

// 2 points per thread, SoA-packed in half2:
//   X0 = (x0_A, x0_B), X1 = (x1_A, x1_B)
// Layer l (z-form, z = 2x for l>=1; final normalize is scale-invariant):
//   y0 = w00*X0 + w01*X1 + b0   (w duplicated into both halves)
//   y1 = w10*X0 + w11*X1 + b1
//   X0' = tanh(y0) + y0 ; X1' = tanh(y1) + y1
__global__ __launch_bounds__(TPB, 8) void nignet_kernel(
    const float4* __restrict__ pts,   // (N,2): one float4 = 2 points
    const float*  __restrict__ Ws,    // (L,2,2)
    const float*  __restrict__ bs,    // (L,2)
    const float*  __restrict__ fW,    // (2,2)
    float4* __restrict__ out,
    int nf4,
    int layers)
{
    __shared__ __align__(16) __half2 sw[MAX_LAYERS][4];  // w00,w01,w10,w11 dup'd
    __shared__ __align__(8)  __half2 sb[MAX_LAYERS][2];  // b0,b1 dup'd
    __shared__ float sf[4];

    const int tid = threadIdx.x;
    if (tid < layers) {
        const float s = (tid == 0) ? 1.0f : 0.5f;   // fold the residual *0.5 into W
        float4 w = ((const float4*)Ws)[tid];
        sw[tid][0] = __float2half2_rn(w.x * s);
        sw[tid][1] = __float2half2_rn(w.y * s);
        sw[tid][2] = __float2half2_rn(w.z * s);
        sw[tid][3] = __float2half2_rn(w.w * s);
        float2 b = ((const float2*)bs)[tid];
        sb[tid][0] = __float2half2_rn(b.x);
        sb[tid][1] = __float2half2_rn(b.y);
    }
    if (tid < 4) sf[tid] = fW[tid];
    __syncthreads();

    const int idx = blockIdx.x * TPB + tid;
    if (idx >= nf4) return;

    float4 v = pts[idx];                       // point A = (v.x,v.y), B = (v.z,v.w)
    __half2 X0 = __floats2half2_rn(v.x, v.z);  // (x0_A, x0_B)
    __half2 X1 = __floats2half2_rn(v.y, v.w);  // (x1_A, x1_B)

    #pragma unroll 4
    for (int l = 0; l < layers; ++l) {
        const __half2 w00 = sw[l][0], w01 = sw[l][1];
        const __half2 w10 = sw[l][2], w11 = sw[l][3];
        const __half2 b0  = sb[l][0], b1  = sb[l][1];
        __half2 y0 = __hfma2(w00, X0, __hfma2(w01, X1, b0));
        __half2 y1 = __hfma2(w10, X0, __hfma2(w11, X1, b1));
        __half2 t0 = tanh_h2(y0);
        __half2 t1 = tanh_h2(y1);
        X0 = __hadd2(t0, y0);
        X1 = __hadd2(t1, y1);
    }

    // Epilogue in fp32: final matvec + L2 row-normalize.
    const float f00 = sf[0], f01 = sf[1], f10 = sf[2], f11 = sf[3];
    const float2 a0 = __half22float2(X0);   // (x0_A, x0_B)
    const float2 a1 = __half22float2(X1);   // (x1_A, x1_B)

    float4 r;
    {
        float o0 = fmaf(f00, a0.x, f01 * a1.x);
        float o1 = fmaf(f10, a0.x, f11 * a1.x);
        float s  = fmaf(o0, o0, o1 * o1);
        float inv = rsqrtf(s);
        inv = inv * fmaf(-0.5f * s * inv, inv, 1.5f);   // one Newton step
        if (s < 1e-24f) inv = 1e12f;                    // eps=1e-12 clamp
        r.x = o0 * inv;
        r.y = o1 * inv;
    }
    {
        float o0 = fmaf(f00, a0.y, f01 * a1.y);
        float o1 = fmaf(f10, a0.y, f11 * a1.y);
        float s  = fmaf(o0, o0, o1 * o1);
        float inv = rsqrtf(s);
        inv = inv * fmaf(-0.5f * s * inv, inv, 1.5f);
        if (s < 1e-24f) inv = 1e12f;
        r.z = o0 * inv;
        r.w = o1 * inv;
    }
    out[idx] = r;
}

extern "C" void kernel_launch(void* const* d_in, const int* in_sizes, int n_in,
                              void* d_out, int out_size) {
    // metadata order: T(1), closed_manifold(N*2), Ws(L*4), bs(L*2), final_W(4)
    const float* pts = (const float*)d_in[1];
    const float* Ws  = (const float*)d_in[2];
    const float* bs  = (const float*)d_in[3];
    const float* fW  = (const float*)d_in[4];
    float* out = (float*)d_out;

    const int n      = in_sizes[1] / 2;   // number of points
    const int layers = in_sizes[2] / 4;   // 64
    const int nf4    = n / 2;             // 2 points per float4

    const int grid = (nf4 + TPB - 1) / TPB;
    nignet_kernel<<<grid, TPB>>>(
        (const float4*)pts, Ws, bs, fW, (float4*)out, nf4, layers);
}